// round 14
// baseline (speedup 1.0000x reference)
#include <cuda_runtime.h>

// Problem constants
constexpr int Bn   = 128;
constexpr int Ln   = 336;
constexpr int Nn   = 321;
constexpr int En   = 128;
constexpr int LATn = 64;

constexpr int HN    = Bn * Nn * En;    // 5,259,264
constexpr int LATSZ = Bn * Nn * LATn;  // 2,629,632

// Scratch: x transposed to [B, N, L] (55 MB, static device global — allowed)
__device__ static float g_xp[(size_t)Bn * Nn * Ln];

// ---------------------------------------------------------------------------
// f32x2 packed-math helpers
// ---------------------------------------------------------------------------
typedef unsigned long long u64t;

__device__ __forceinline__ u64t ffma2(u64t a, u64t b, u64t c) {
    u64t d;
    asm("fma.rn.f32x2 %0, %1, %2, %3;" : "=l"(d) : "l"(a), "l"(b), "l"(c));
    return d;
}
__device__ __forceinline__ u64t bcast2(float w) {
    u64t d;
    asm("mov.b64 %0, {%1, %1};" : "=l"(d) : "f"(w));
    return d;
}
__device__ __forceinline__ float2 unpk(u64t v) {
    float2 r;
    asm("mov.b64 {%0, %1}, %2;" : "=f"(r.x), "=f"(r.y) : "l"(v));
    return r;
}
__device__ __forceinline__ u64t pack2(float lo, float hi) {
    u64t d;
    asm("mov.b64 %0, {%1, %2};" : "=l"(d) : "f"(lo), "f"(hi));
    return d;
}

// ---------------------------------------------------------------------------
// Kernel 1: transpose x [B, L, N] -> g_xp [B, N, L]  (unchanged, ~22us)
// ---------------------------------------------------------------------------
__global__ void transpose_kernel(const float* __restrict__ x) {
    __shared__ float tile[32][33];
    const int b  = blockIdx.z;
    const int n0 = blockIdx.x * 32;
    const int l0 = blockIdx.y * 32;

#pragma unroll
    for (int i = 0; i < 4; i++) {
        int l  = l0 + threadIdx.y + i * 8;
        int nn = n0 + threadIdx.x;
        if (l < Ln && nn < Nn)
            tile[threadIdx.y + i * 8][threadIdx.x] = x[((size_t)b * Ln + l) * Nn + nn];
    }
    __syncthreads();
#pragma unroll
    for (int i = 0; i < 4; i++) {
        int nn = n0 + threadIdx.y + i * 8;
        int l  = l0 + threadIdx.x;
        if (nn < Nn && l < Ln)
            g_xp[((size_t)b * Nn + nn) * Ln + l] = tile[threadIdx.x][threadIdx.y + i * 8];
    }
}

// ---------------------------------------------------------------------------
// Kernel 2 (FUSED): per (n, 64-batch-slab) CTA.
//   Phase 1 (LK=56): h = xp @ W_embed + b_embed
//            epilogue: write h, h_hat = sigmoid(time_x)*h  (gmem + smem hsT)
//   Phase 2: mu/var = hsT @ [W_mu|W_var] + bias, A resident in smem.
// Changes vs R12: BMP 66->68 (16B-aligned rows) so x-pair loads use
//                 2x LDS.128 instead of 4x LDS.64 -> LDS wavefronts 8->6/kstep.
// ---------------------------------------------------------------------------
constexpr int BM2 = 64;   // batch rows per CTA
constexpr int LK  = 56;   // phase-1 k-tile (336 = 6*56)
constexpr int BMP = 68;   // padded row width: 272B = 17*16 -> LDS.128-aligned
constexpr int KT3 = 16;   // phase-2 k-tile (128 = 8*16)

// smem overlay (bytes):
//  phase1: xs[56][68] f32 (15232)  | ws[56][128] f32 (28672)  -> 43904
//  phase2: hsT[128][68] f32 (34816)| ws3[16][128] f32 (8192)  -> 43008
constexpr int SM_XS   = 0;
constexpr int SM_WS   = 15232;
constexpr int SM_HST  = 0;
constexpr int SM_WS3  = 34816;
constexpr int SM_BYTES = 43904;

__global__ void __launch_bounds__(256, 3) fused_kernel(
    const float* __restrict__ W_embed, const float* __restrict__ b_embed,
    const float* __restrict__ time_x,
    const float* __restrict__ W_mu, const float* __restrict__ b_mu,
    const float* __restrict__ W_var, const float* __restrict__ b_var,
    float* __restrict__ h_out, float* __restrict__ hhat_out,
    float* __restrict__ mu_out, float* __restrict__ var_out)
{
    __shared__ __align__(16) char smem[SM_BYTES];
    float (*xs)[BMP]  = (float (*)[BMP])(smem + SM_XS);    // [LK][BMP]
    float (*ws)[En]   = (float (*)[En]) (smem + SM_WS);    // [LK][128]
    float (*hsT)[BMP] = (float (*)[BMP])(smem + SM_HST);   // [128][BMP]
    float (*ws3)[128] = (float (*)[128])(smem + SM_WS3);   // [KT3][128]

    const int n    = blockIdx.x;
    const int b0   = blockIdx.y * BM2;
    const int t    = threadIdx.x;
    const int lane = t & 31;
    const int wid  = t >> 5;
    const int m_base = wid * 8;

    // ===================== Phase 1: embed GEMM =============================
    u64t acc[4][4];
#pragma unroll
    for (int p = 0; p < 4; p++)
#pragma unroll
        for (int j = 0; j < 4; j++) acc[p][j] = 0ULL;

    for (int kt = 0; kt < Ln; kt += LK) {
        // fill xs: 64 x 56 (coalesced reads along L)
#pragma unroll
        for (int i = 0; i < (BM2 * LK) / 256; i++) {
            int idx = t + i * 256;
            int m = idx / LK;
            int kk = idx - m * LK;
            xs[kk][m] = g_xp[((size_t)(b0 + m) * Nn + n) * Ln + kt + kk];
        }
        // fill ws: 56 x 128, float4 vectorized (7 iters of LDG.128/STS.128)
#pragma unroll
        for (int i = 0; i < (LK * En) / (256 * 4); i++) {
            int idx = t + i * 256;       // quad index
            int kk = idx >> 5;           // /32 quads per row
            int e4 = (idx & 31) * 4;
            *(float4*)&ws[kk][e4] =
                *(const float4*)&W_embed[((size_t)n * Ln + kt + kk) * En + e4];
        }
        __syncthreads();

#pragma unroll
        for (int kk = 0; kk < LK; kk++) {
            // 8 contiguous floats = 4 pairs via 2x LDS.128 (broadcast)
            ulonglong2 xA = *reinterpret_cast<const ulonglong2*>(&xs[kk][m_base]);
            ulonglong2 xB = *reinterpret_cast<const ulonglong2*>(&xs[kk][m_base + 4]);
            u64t xpair[4] = {xA.x, xA.y, xB.x, xB.y};
#pragma unroll
            for (int j = 0; j < 4; j++) {
                u64t w2 = bcast2(ws[kk][lane + 32 * j]);
#pragma unroll
                for (int p = 0; p < 4; p++)
                    acc[p][j] = ffma2(xpair[p], w2, acc[p][j]);
            }
        }
        __syncthreads();
    }

    // Phase-1 epilogue: bias + h -> gmem ; h_hat -> gmem AND smem hsT[e][m]
#pragma unroll
    for (int j = 0; j < 4; j++) {
        const int e = lane + 32 * j;
        const float bias = b_embed[n * En + e];
#pragma unroll
        for (int p = 0; p < 4; p++) {
            float2 hv = unpk(acc[p][j]);
            const int mloc = m_base + 2 * p;
            const int b_r = b0 + mloc;
            const size_t i0 = ((size_t)b_r * Nn + n) * En + e;
            const size_t i1 = i0 + (size_t)Nn * En;
            float h0 = hv.x + bias;
            float h1 = hv.y + bias;
            h_out[i0] = h0;
            h_out[i1] = h1;
            float t0 = time_x[i0];
            float t1 = time_x[i1];
            float g0 = h0 / (1.0f + __expf(-t0));
            float g1 = h1 / (1.0f + __expf(-t1));
            hhat_out[i0] = g0;
            hhat_out[i1] = g1;
            *reinterpret_cast<u64t*>(&hsT[e][mloc]) = pack2(g0, g1);
        }
    }
    __syncthreads();   // hsT fully written before phase 2 reads

    // ===================== Phase 2: mu/var heads (A resident in hsT) =======
#pragma unroll
    for (int p = 0; p < 4; p++)
#pragma unroll
        for (int j = 0; j < 4; j++) acc[p][j] = 0ULL;

    for (int kt = 0; kt < En; kt += KT3) {
        // fill ws3: 16 k x (64 mu | 64 var), float4 vectorized (2 iters)
#pragma unroll
        for (int i = 0; i < (KT3 * 128) / (256 * 4); i++) {
            int idx = t + i * 256;       // quad index
            int kk = idx >> 5;
            int c4 = (idx & 31) * 4;
            float4 v;
            if (c4 < 64)
                v = *(const float4*)&W_mu[((size_t)n * En + kt + kk) * LATn + c4];
            else
                v = *(const float4*)&W_var[((size_t)n * En + kt + kk) * LATn + (c4 - 64)];
            *(float4*)&ws3[kk][c4] = v;
        }
        __syncthreads();

#pragma unroll
        for (int kk = 0; kk < KT3; kk++) {
            ulonglong2 xA = *reinterpret_cast<const ulonglong2*>(&hsT[kt + kk][m_base]);
            ulonglong2 xB = *reinterpret_cast<const ulonglong2*>(&hsT[kt + kk][m_base + 4]);
            u64t xpair[4] = {xA.x, xA.y, xB.x, xB.y};
#pragma unroll
            for (int j = 0; j < 4; j++) {
                u64t w2 = bcast2(ws3[kk][lane + 32 * j]);
#pragma unroll
                for (int p = 0; p < 4; p++)
                    acc[p][j] = ffma2(xpair[p], w2, acc[p][j]);
            }
        }
        __syncthreads();
    }

    // Phase-2 epilogue: j=0,1 -> mu cols, j=2,3 -> var cols
#pragma unroll
    for (int j = 0; j < 4; j++) {
        const int c = lane + 32 * j;
        const bool is_mu = (c < 64);
        const int col = is_mu ? c : (c - 64);
        const float bias = is_mu ? b_mu[n * LATn + col] : b_var[n * LATn + col];
        float* __restrict__ dst = is_mu ? mu_out : var_out;
#pragma unroll
        for (int p = 0; p < 4; p++) {
            float2 hv = unpk(acc[p][j]);
            const int b_r = b0 + m_base + 2 * p;
            const size_t i0 = ((size_t)b_r * Nn + n) * LATn + col;
            const size_t i1 = i0 + (size_t)Nn * LATn;
            dst[i0] = hv.x + bias;
            dst[i1] = hv.y + bias;
        }
    }
}

// ---------------------------------------------------------------------------
// Launch
// ---------------------------------------------------------------------------
extern "C" void kernel_launch(void* const* d_in, const int* in_sizes, int n_in,
                              void* d_out, int out_size) {
    const float* x       = (const float*)d_in[0];
    const float* time_x  = (const float*)d_in[1];
    const float* W_embed = (const float*)d_in[2];
    const float* b_embed = (const float*)d_in[3];
    const float* W_mu    = (const float*)d_in[4];
    const float* b_mu    = (const float*)d_in[5];
    const float* W_var   = (const float*)d_in[6];
    const float* b_var   = (const float*)d_in[7];

    float* out  = (float*)d_out;
    float* h    = out;
    float* hhat = out + HN;
    float* mu   = out + 2 * HN;
    float* var  = out + 2 * HN + LATSZ;

    dim3 tgrid((Nn + 31) / 32, (Ln + 31) / 32, Bn);
    transpose_kernel<<<tgrid, dim3(32, 8)>>>(x);

    fused_kernel<<<dim3(Nn, Bn / BM2), 256>>>(
        W_embed, b_embed, time_x, W_mu, b_mu, W_var, b_var,
        h, hhat, mu, var);
}

// round 15
// speedup vs baseline: 1.1553x; 1.1553x over previous
#include <cuda_runtime.h>
#include <cstdint>

// Problem constants
constexpr int Bn   = 128;
constexpr int Ln   = 336;
constexpr int Nn   = 321;
constexpr int En   = 128;
constexpr int LATn = 64;

constexpr int HN    = Bn * Nn * En;    // 5,259,264
constexpr int LATSZ = Bn * Nn * LATn;  // 2,629,632

// Scratch: x transposed to [B, N, L] (55 MB, static device global — allowed)
__device__ static float g_xp[(size_t)Bn * Nn * Ln];

// ---------------------------------------------------------------------------
// f32x2 packed-math + cp.async helpers
// ---------------------------------------------------------------------------
typedef unsigned long long u64t;

__device__ __forceinline__ u64t ffma2(u64t a, u64t b, u64t c) {
    u64t d;
    asm("fma.rn.f32x2 %0, %1, %2, %3;" : "=l"(d) : "l"(a), "l"(b), "l"(c));
    return d;
}
__device__ __forceinline__ u64t bcast2(float w) {
    u64t d;
    asm("mov.b64 %0, {%1, %1};" : "=l"(d) : "f"(w));
    return d;
}
__device__ __forceinline__ float2 unpk(u64t v) {
    float2 r;
    asm("mov.b64 {%0, %1}, %2;" : "=f"(r.x), "=f"(r.y) : "l"(v));
    return r;
}
__device__ __forceinline__ u64t pack2(float lo, float hi) {
    u64t d;
    asm("mov.b64 %0, {%1, %2};" : "=l"(d) : "f"(lo), "f"(hi));
    return d;
}
__device__ __forceinline__ void cpa4(uint32_t s, const void* g) {
    asm volatile("cp.async.ca.shared.global [%0], [%1], 4;" :: "r"(s), "l"(g));
}
__device__ __forceinline__ void cpa16(uint32_t s, const void* g) {
    asm volatile("cp.async.cg.shared.global [%0], [%1], 16;" :: "r"(s), "l"(g));
}
__device__ __forceinline__ void cpa_commit() {
    asm volatile("cp.async.commit_group;" ::: "memory");
}
__device__ __forceinline__ void cpa_wait0() {
    asm volatile("cp.async.wait_group 0;" ::: "memory");
}

// ---------------------------------------------------------------------------
// Kernel 1: transpose x [B, L, N] -> g_xp [B, N, L]  (unchanged, ~22us)
// ---------------------------------------------------------------------------
__global__ void transpose_kernel(const float* __restrict__ x) {
    __shared__ float tile[32][33];
    const int b  = blockIdx.z;
    const int n0 = blockIdx.x * 32;
    const int l0 = blockIdx.y * 32;

#pragma unroll
    for (int i = 0; i < 4; i++) {
        int l  = l0 + threadIdx.y + i * 8;
        int nn = n0 + threadIdx.x;
        if (l < Ln && nn < Nn)
            tile[threadIdx.y + i * 8][threadIdx.x] = x[((size_t)b * Ln + l) * Nn + nn];
    }
    __syncthreads();
#pragma unroll
    for (int i = 0; i < 4; i++) {
        int nn = n0 + threadIdx.y + i * 8;
        int l  = l0 + threadIdx.x;
        if (nn < Nn && l < Ln)
            g_xp[((size_t)b * Nn + nn) * Ln + l] = tile[threadIdx.x][threadIdx.y + i * 8];
    }
}

// ---------------------------------------------------------------------------
// Kernel 2 (FUSED): per (n, 64-batch-slab) CTA.
//   Phase 1: h = xp @ W_embed + b, LK=24, 14 tiles, cp.async double-buffered.
//   Phase 2: mu/var = hsT @ [W_mu|W_var] + bias, KT3=8, 16 tiles, ws3 dbuf.
// Inner loop = R12 structure (best measured): 4x LDS.64 bcast + 4x LDS.32.
// ---------------------------------------------------------------------------
constexpr int BM2 = 64;   // batch rows per CTA
constexpr int LK  = 24;   // phase-1 k-tile (336 = 14*24)
constexpr int NT1 = Ln / LK;   // 14
constexpr int BMP = 66;   // padded row width (8B-aligned pairs)
constexpr int KT3 = 8;    // phase-2 k-tile (128 = 16*8)
constexpr int NT2 = En / KT3;  // 16

// smem overlay (bytes):
//  phase1: xs[2][24][66] (12672) | ws[2][24][128] (24576)  -> 37248
//  phase2: hsT[128][66]  (33792) | ws3[2][8][128] (8192)   -> 41984
constexpr int SM_XS   = 0;
constexpr int SM_WS   = 12672;
constexpr int SM_HST  = 0;
constexpr int SM_WS3  = 33792;
constexpr int SM_BYTES = 41984;

__global__ void __launch_bounds__(256, 3) fused_kernel(
    const float* __restrict__ W_embed, const float* __restrict__ b_embed,
    const float* __restrict__ time_x,
    const float* __restrict__ W_mu, const float* __restrict__ b_mu,
    const float* __restrict__ W_var, const float* __restrict__ b_var,
    float* __restrict__ h_out, float* __restrict__ hhat_out,
    float* __restrict__ mu_out, float* __restrict__ var_out)
{
    __shared__ __align__(16) char smem[SM_BYTES];
    const uint32_t smem_u32 = (uint32_t)__cvta_generic_to_shared(smem);

    float (*hsT)[BMP] = (float (*)[BMP])(smem + SM_HST);   // [128][BMP]

    const int n    = blockIdx.x;
    const int b0   = blockIdx.y * BM2;
    const int t    = threadIdx.x;
    const int lane = t & 31;
    const int wid  = t >> 5;
    const int m_base = wid * 8;

    // ===================== Phase 1: embed GEMM =============================
    u64t acc[4][4];
#pragma unroll
    for (int p = 0; p < 4; p++)
#pragma unroll
        for (int j = 0; j < 4; j++) acc[p][j] = 0ULL;

    // per-thread fill coordinates (constant across tiles)
    // xs: 6 scalar elements; ws: 3 quads
    const int xm0 = t / LK;          // via 6 strided idx below
    (void)xm0;

    auto issue_fill1 = [&](int kt, int buf) {
#pragma unroll
        for (int i = 0; i < (BM2 * LK) / 256; i++) {
            int idx = t + i * 256;
            int m = idx / LK;
            int kk = idx - m * LK;
            uint32_t dst = smem_u32 + SM_XS + (((buf * LK + kk) * BMP) + m) * 4;
            cpa4(dst, &g_xp[((size_t)(b0 + m) * Nn + n) * Ln + kt + kk]);
        }
#pragma unroll
        for (int i = 0; i < (LK * En) / (256 * 4); i++) {
            int idx = t + i * 256;       // quad index
            int kk = idx >> 5;
            int e4 = (idx & 31) * 4;
            uint32_t dst = smem_u32 + SM_WS + (((buf * LK + kk) * En) + e4) * 4;
            cpa16(dst, &W_embed[((size_t)n * Ln + kt + kk) * En + e4]);
        }
        cpa_commit();
    };

    issue_fill1(0, 0);
    for (int tt = 0; tt < NT1; tt++) {
        const int p = tt & 1;
        cpa_wait0();
        __syncthreads();
        if (tt + 1 < NT1) issue_fill1((tt + 1) * LK, 1 - p);

        const float (*xsb)[BMP] = (const float (*)[BMP])(smem + SM_XS + p * LK * BMP * 4);
        const float (*wsb)[En]  = (const float (*)[En]) (smem + SM_WS + p * LK * En * 4);

#pragma unroll
        for (int kk = 0; kk < LK; kk++) {
            u64t xpair[4];
#pragma unroll
            for (int q = 0; q < 4; q++)
                xpair[q] = *reinterpret_cast<const u64t*>(&xsb[kk][m_base + 2 * q]);
#pragma unroll
            for (int j = 0; j < 4; j++) {
                u64t w2 = bcast2(wsb[kk][lane + 32 * j]);
#pragma unroll
                for (int q = 0; q < 4; q++)
                    acc[q][j] = ffma2(xpair[q], w2, acc[q][j]);
            }
        }
    }
    __syncthreads();   // all warps done reading xs/ws before hsT overlays them

    // Phase-1 epilogue: bias + h -> gmem ; h_hat -> gmem AND smem hsT[e][m]
#pragma unroll
    for (int j = 0; j < 4; j++) {
        const int e = lane + 32 * j;
        const float bias = b_embed[n * En + e];
#pragma unroll
        for (int p = 0; p < 4; p++) {
            float2 hv = unpk(acc[p][j]);
            const int mloc = m_base + 2 * p;
            const int b_r = b0 + mloc;
            const size_t i0 = ((size_t)b_r * Nn + n) * En + e;
            const size_t i1 = i0 + (size_t)Nn * En;
            float h0 = hv.x + bias;
            float h1 = hv.y + bias;
            h_out[i0] = h0;
            h_out[i1] = h1;
            float t0 = time_x[i0];
            float t1 = time_x[i1];
            float g0 = h0 / (1.0f + __expf(-t0));
            float g1 = h1 / (1.0f + __expf(-t1));
            hhat_out[i0] = g0;
            hhat_out[i1] = g1;
            *reinterpret_cast<u64t*>(&hsT[e][mloc]) = pack2(g0, g1);
        }
    }
    __syncthreads();   // hsT fully written before phase 2 reads

    // ===================== Phase 2: mu/var heads (A resident in hsT) =======
#pragma unroll
    for (int p = 0; p < 4; p++)
#pragma unroll
        for (int j = 0; j < 4; j++) acc[p][j] = 0ULL;

    auto issue_fill2 = [&](int kt, int buf) {
        // 8 k x 128 cols = 256 quads -> 1 quad per thread
        int kk = t >> 5;
        int c4 = (t & 31) * 4;
        uint32_t dst = smem_u32 + SM_WS3 + (((buf * KT3 + kk) * 128) + c4) * 4;
        const float* src = (c4 < 64)
            ? &W_mu [((size_t)n * En + kt + kk) * LATn + c4]
            : &W_var[((size_t)n * En + kt + kk) * LATn + (c4 - 64)];
        cpa16(dst, src);
        cpa_commit();
    };

    issue_fill2(0, 0);
    for (int tt = 0; tt < NT2; tt++) {
        const int p = tt & 1;
        cpa_wait0();
        __syncthreads();
        if (tt + 1 < NT2) issue_fill2((tt + 1) * KT3, 1 - p);

        const int kt = tt * KT3;
        const float (*ws3b)[128] = (const float (*)[128])(smem + SM_WS3 + p * KT3 * 128 * 4);

#pragma unroll
        for (int kk = 0; kk < KT3; kk++) {
            u64t xpair[4];
#pragma unroll
            for (int q = 0; q < 4; q++)
                xpair[q] = *reinterpret_cast<const u64t*>(&hsT[kt + kk][m_base + 2 * q]);
#pragma unroll
            for (int j = 0; j < 4; j++) {
                u64t w2 = bcast2(ws3b[kk][lane + 32 * j]);
#pragma unroll
                for (int q = 0; q < 4; q++)
                    acc[q][j] = ffma2(xpair[q], w2, acc[q][j]);
            }
        }
    }

    // Phase-2 epilogue: j=0,1 -> mu cols, j=2,3 -> var cols
#pragma unroll
    for (int j = 0; j < 4; j++) {
        const int c = lane + 32 * j;
        const bool is_mu = (c < 64);
        const int col = is_mu ? c : (c - 64);
        const float bias = is_mu ? b_mu[n * LATn + col] : b_var[n * LATn + col];
        float* __restrict__ dst = is_mu ? mu_out : var_out;
#pragma unroll
        for (int p = 0; p < 4; p++) {
            float2 hv = unpk(acc[p][j]);
            const int b_r = b0 + m_base + 2 * p;
            const size_t i0 = ((size_t)b_r * Nn + n) * LATn + col;
            const size_t i1 = i0 + (size_t)Nn * LATn;
            dst[i0] = hv.x + bias;
            dst[i1] = hv.y + bias;
        }
    }
}

// ---------------------------------------------------------------------------
// Launch
// ---------------------------------------------------------------------------
extern "C" void kernel_launch(void* const* d_in, const int* in_sizes, int n_in,
                              void* d_out, int out_size) {
    const float* x       = (const float*)d_in[0];
    const float* time_x  = (const float*)d_in[1];
    const float* W_embed = (const float*)d_in[2];
    const float* b_embed = (const float*)d_in[3];
    const float* W_mu    = (const float*)d_in[4];
    const float* b_mu    = (const float*)d_in[5];
    const float* W_var   = (const float*)d_in[6];
    const float* b_var   = (const float*)d_in[7];

    float* out  = (float*)d_out;
    float* h    = out;
    float* hhat = out + HN;
    float* mu   = out + 2 * HN;
    float* var  = out + 2 * HN + LATSZ;

    dim3 tgrid((Nn + 31) / 32, (Ln + 31) / 32, Bn);
    transpose_kernel<<<tgrid, dim3(32, 8)>>>(x);

    fused_kernel<<<dim3(Nn, Bn / BM2), 256>>>(
        W_embed, b_embed, time_x, W_mu, b_mu, W_var, b_var,
        h, hhat, mu, var);
}